// round 2
// baseline (speedup 1.0000x reference)
#include <cuda_runtime.h>

#define BN_EPS   1e-5f
#define DIST_EPS 1e-8f

#define BB 8
#define NN 16384
#define SS 2048
#define D1C 128
#define D2C 256
#define MM (BB*NN)      /* 131072 */
#define M2 (BB*SS)      /* 16384 */
#define C1 256
#define C2 128
#define W1STRIDE 384

// ---------------- scratch (device globals; no allocations) ----------------
__device__ __align__(16) float g_p2w[(size_t)M2 * C1];       // 16 MB (L2-resident)
__device__ __align__(16) float g_h1[(size_t)MM * C1];        // 134 MB
__device__ __align__(16) float g_h2[(size_t)MM * C2];        // 67 MB
__device__ int   g_idx3[MM * 3];
__device__ float g_w3[MM * 3];
__device__ float g_bn1s[C1], g_bn1q[C1];
__device__ float g_bn2s[C2], g_bn2q[C2];
__device__ __align__(16) float g_a1[C1], g_c1[C1];
__device__ __align__(16) float g_a2[C2], g_c2[C2];
__device__ float g_poolsum[BB * C2];
__device__ int   g_poolmax[BB * C2];          // float-as-int, all values >= 0
__device__ __align__(16) float g_scale[BB * C2];

// ---------------- init: zero per-replay accumulators ----------------
__global__ void init_kernel() {
    int t = threadIdx.x;
    if (t < C1) { g_bn1s[t] = 0.f; g_bn1q[t] = 0.f; }
    if (t < C2) { g_bn2s[t] = 0.f; g_bn2q[t] = 0.f; }
    for (int i = t; i < BB * C2; i += blockDim.x) {
        g_poolsum[i] = 0.f;
        g_poolmax[i] = 0;
    }
}

// ---------------- 3-NN search ----------------
__global__ __launch_bounds__(256) void nn3_kernel(
    const float* __restrict__ xyz1, const float* __restrict__ xyz2) {
    __shared__ float sx[SS], sy[SS], sz[SS];
    int b = blockIdx.y;
    const float* x2 = xyz2 + (size_t)b * SS * 3;
    for (int j = threadIdx.x; j < SS; j += blockDim.x) {
        sx[j] = x2[j * 3 + 0];
        sy[j] = x2[j * 3 + 1];
        sz[j] = x2[j * 3 + 2];
    }
    __syncthreads();
    int n = blockIdx.x * blockDim.x + threadIdx.x;
    int m = b * NN + n;
    float px = xyz1[(size_t)m * 3 + 0];
    float py = xyz1[(size_t)m * 3 + 1];
    float pz = xyz1[(size_t)m * 3 + 2];
    float d0 = 1e30f, d1 = 1e30f, d2 = 1e30f;
    int i0 = 0, i1 = 0, i2 = 0;
#pragma unroll 4
    for (int j = 0; j < SS; j++) {
        float dx = px - sx[j], dy = py - sy[j], dz = pz - sz[j];
        float d = fmaf(dx, dx, fmaf(dy, dy, dz * dz));
        if (d < d2) {
            if (d < d1) {
                d2 = d1; i2 = i1;
                if (d < d0) { d1 = d0; i1 = i0; d0 = d; i0 = j; }
                else        { d1 = d;  i1 = j; }
            } else { d2 = d; i2 = j; }
        }
    }
    float r0 = 1.f / (d0 + DIST_EPS);
    float r1 = 1.f / (d1 + DIST_EPS);
    float r2 = 1.f / (d2 + DIST_EPS);
    float rs = 1.f / (r0 + r1 + r2);
    g_idx3[m * 3 + 0] = i0; g_idx3[m * 3 + 1] = i1; g_idx3[m * 3 + 2] = i2;
    g_w3[m * 3 + 0] = r0 * rs; g_w3[m * 3 + 1] = r1 * rs; g_w3[m * 3 + 2] = r2 * rs;
}

// ---------------- P2W: [16384,256] x W1b[256->256]  (w1 cols 128..383) ----------------
__global__ __launch_bounds__(256) void p2w_kernel(
    const float* __restrict__ points2, const float* __restrict__ w1) {
    __shared__ float As[16][128];
    __shared__ float Bs[16][128];
    int tid = threadIdx.x;
    int tr = tid >> 4, tc = tid & 15;
    int rowTile = blockIdx.x << 7;
    int colTile = blockIdx.y << 7;
    float acc[8][8] = {};
    for (int k0 = 0; k0 < D2C; k0 += 16) {
#pragma unroll
        for (int l = 0; l < 2; l++) {
            int lin = tid + (l << 8);
            int r = lin >> 2, c4 = lin & 3;
            float4 v = *(const float4*)(points2 + (size_t)(rowTile + r) * D2C + k0 + (c4 << 2));
            As[(c4 << 2) + 0][r] = v.x; As[(c4 << 2) + 1][r] = v.y;
            As[(c4 << 2) + 2][r] = v.z; As[(c4 << 2) + 3][r] = v.w;
        }
#pragma unroll
        for (int l = 0; l < 2; l++) {
            int lin = tid + (l << 8);
            int o = lin >> 2, c4 = lin & 3;
            float4 v = *(const float4*)(w1 + (size_t)(colTile + o) * W1STRIDE + D1C + k0 + (c4 << 2));
            Bs[(c4 << 2) + 0][o] = v.x; Bs[(c4 << 2) + 1][o] = v.y;
            Bs[(c4 << 2) + 2][o] = v.z; Bs[(c4 << 2) + 3][o] = v.w;
        }
        __syncthreads();
#pragma unroll
        for (int k = 0; k < 16; k++) {
            float af[8], bf[8];
            *(float4*)(af)     = *(const float4*)&As[k][tr << 2];
            *(float4*)(af + 4) = *(const float4*)&As[k][64 + (tr << 2)];
            *(float4*)(bf)     = *(const float4*)&Bs[k][tc << 2];
            *(float4*)(bf + 4) = *(const float4*)&Bs[k][64 + (tc << 2)];
#pragma unroll
            for (int i = 0; i < 8; i++)
#pragma unroll
                for (int j = 0; j < 8; j++)
                    acc[i][j] = fmaf(af[i], bf[j], acc[i][j]);
        }
        __syncthreads();
    }
#pragma unroll
    for (int i = 0; i < 8; i++) {
        int rl = (i < 4) ? (tr * 4 + i) : (64 + tr * 4 + i - 4);
        float* dst = g_p2w + (size_t)(rowTile + rl) * C1 + colTile;
        *(float4*)(dst + tc * 4)      = make_float4(acc[i][0], acc[i][1], acc[i][2], acc[i][3]);
        *(float4*)(dst + 64 + tc * 4) = make_float4(acc[i][4], acc[i][5], acc[i][6], acc[i][7]);
    }
}

// ---- GEMM1: points1[M,128] x W1a[128->256] + gathered P2W + bias; bn-stats epilogue ----
__global__ __launch_bounds__(256) void gemm1_kernel(
    const float* __restrict__ points1, const float* __restrict__ w1,
    const float* __restrict__ bias) {
    __shared__ float As[16][128];
    __shared__ float Bs[16][128];
    __shared__ int   sIdx[128][3];
    __shared__ float sW[128][3];
    int tid = threadIdx.x;
    int tr = tid >> 4, tc = tid & 15;
    int rowTile = blockIdx.x << 7;
    int colTile = blockIdx.y << 7;
    int bBlk = rowTile >> 14;                 // all 128 rows in same batch
    if (tid < 128) {
        int m = rowTile + tid;
        sIdx[tid][0] = g_idx3[m * 3 + 0];
        sIdx[tid][1] = g_idx3[m * 3 + 1];
        sIdx[tid][2] = g_idx3[m * 3 + 2];
        sW[tid][0] = g_w3[m * 3 + 0];
        sW[tid][1] = g_w3[m * 3 + 1];
        sW[tid][2] = g_w3[m * 3 + 2];
    }
    float acc[8][8] = {};
    for (int k0 = 0; k0 < D1C; k0 += 16) {
#pragma unroll
        for (int l = 0; l < 2; l++) {
            int lin = tid + (l << 8);
            int r = lin >> 2, c4 = lin & 3;
            float4 v = *(const float4*)(points1 + (size_t)(rowTile + r) * D1C + k0 + (c4 << 2));
            As[(c4 << 2) + 0][r] = v.x; As[(c4 << 2) + 1][r] = v.y;
            As[(c4 << 2) + 2][r] = v.z; As[(c4 << 2) + 3][r] = v.w;
        }
#pragma unroll
        for (int l = 0; l < 2; l++) {
            int lin = tid + (l << 8);
            int o = lin >> 2, c4 = lin & 3;
            float4 v = *(const float4*)(w1 + (size_t)(colTile + o) * W1STRIDE + k0 + (c4 << 2));
            Bs[(c4 << 2) + 0][o] = v.x; Bs[(c4 << 2) + 1][o] = v.y;
            Bs[(c4 << 2) + 2][o] = v.z; Bs[(c4 << 2) + 3][o] = v.w;
        }
        __syncthreads();
#pragma unroll
        for (int k = 0; k < 16; k++) {
            float af[8], bf[8];
            *(float4*)(af)     = *(const float4*)&As[k][tr << 2];
            *(float4*)(af + 4) = *(const float4*)&As[k][64 + (tr << 2)];
            *(float4*)(bf)     = *(const float4*)&Bs[k][tc << 2];
            *(float4*)(bf + 4) = *(const float4*)&Bs[k][64 + (tc << 2)];
#pragma unroll
            for (int i = 0; i < 8; i++)
#pragma unroll
                for (int j = 0; j < 8; j++)
                    acc[i][j] = fmaf(af[i], bf[j], acc[i][j]);
        }
        __syncthreads();
    }
    float bv[8];
#pragma unroll
    for (int j = 0; j < 8; j++) {
        int cl = (j < 4) ? (tc * 4 + j) : (64 + tc * 4 + j - 4);
        bv[j] = bias[colTile + cl];
    }
    const float* Pbase = g_p2w + (size_t)bBlk * SS * C1 + colTile;
    float csum[8] = {}, csq[8] = {};
#pragma unroll
    for (int i = 0; i < 8; i++) {
        int rl = (i < 4) ? (tr * 4 + i) : (64 + tr * 4 + i - 4);
        int mg = rowTile + rl;
        float w0 = sW[rl][0], w1v = sW[rl][1], w2v = sW[rl][2];
        const float* P0 = Pbase + (size_t)sIdx[rl][0] * C1;
        const float* P1 = Pbase + (size_t)sIdx[rl][1] * C1;
        const float* P2 = Pbase + (size_t)sIdx[rl][2] * C1;
        float4 a0 = *(const float4*)(P0 + tc * 4);
        float4 a1 = *(const float4*)(P1 + tc * 4);
        float4 a2 = *(const float4*)(P2 + tc * 4);
        float4 e0 = *(const float4*)(P0 + 64 + tc * 4);
        float4 e1 = *(const float4*)(P1 + 64 + tc * 4);
        float4 e2 = *(const float4*)(P2 + 64 + tc * 4);
        float gth[8];
        gth[0] = w0 * a0.x + w1v * a1.x + w2v * a2.x;
        gth[1] = w0 * a0.y + w1v * a1.y + w2v * a2.y;
        gth[2] = w0 * a0.z + w1v * a1.z + w2v * a2.z;
        gth[3] = w0 * a0.w + w1v * a1.w + w2v * a2.w;
        gth[4] = w0 * e0.x + w1v * e1.x + w2v * e2.x;
        gth[5] = w0 * e0.y + w1v * e1.y + w2v * e2.y;
        gth[6] = w0 * e0.z + w1v * e1.z + w2v * e2.z;
        gth[7] = w0 * e0.w + w1v * e1.w + w2v * e2.w;
        float o[8];
#pragma unroll
        for (int j = 0; j < 8; j++) {
            float v = acc[i][j] + bv[j] + gth[j];
            o[j] = v;
            csum[j] += v;
            csq[j] = fmaf(v, v, csq[j]);
        }
        float* dst = g_h1 + (size_t)mg * C1 + colTile;
        *(float4*)(dst + tc * 4)      = make_float4(o[0], o[1], o[2], o[3]);
        *(float4*)(dst + 64 + tc * 4) = make_float4(o[4], o[5], o[6], o[7]);
    }
    __syncthreads();
#pragma unroll
    for (int j = 0; j < 8; j++) {
        int cl = (j < 4) ? (tc * 4 + j) : (64 + tc * 4 + j - 4);
        As[tr][cl] = csum[j];
        Bs[tr][cl] = csq[j];
    }
    __syncthreads();
    if (tid < 128) {
        float s = 0.f, q = 0.f;
#pragma unroll
        for (int t = 0; t < 16; t++) { s += As[t][tid]; q += Bs[t][tid]; }
        atomicAdd(&g_bn1s[colTile + tid], s);
        atomicAdd(&g_bn1q[colTile + tid], q);
    }
}

// ---------------- bn param: sums -> (a, c) affine ----------------
__global__ void bnparam_kernel(const float* __restrict__ g,
                               const float* __restrict__ be, int which) {
    int i = threadIdx.x;
    const float invM = 1.0f / (float)MM;
    if (which == 0) {
        if (i < C1) {
            float mu = g_bn1s[i] * invM;
            float var = g_bn1q[i] * invM - mu * mu;
            float a = g[i] * rsqrtf(var + BN_EPS);
            g_a1[i] = a;
            g_c1[i] = fmaf(-mu, a, be[i]);
        }
    } else {
        if (i < C2) {
            float mu = g_bn2s[i] * invM;
            float var = g_bn2q[i] * invM - mu * mu;
            float a = g[i] * rsqrtf(var + BN_EPS);
            g_a2[i] = a;
            g_c2[i] = fmaf(-mu, a, be[i]);
        }
    }
}

// ---------------- GEMM2: relu(bn1(h1)) x [256->128] + bias, bn-stats epilogue ----------------
__global__ __launch_bounds__(256) void gemm2_kernel(
    const float* __restrict__ w2, const float* __restrict__ bias) {
    __shared__ float As[16][128];
    __shared__ float Bs[16][128];
    int tid = threadIdx.x;
    int tr = tid >> 4, tc = tid & 15;
    int rowTile = blockIdx.x << 7;
    float acc[8][8] = {};
    for (int k0 = 0; k0 < C1; k0 += 16) {
#pragma unroll
        for (int l = 0; l < 2; l++) {
            int lin = tid + (l << 8);
            int r = lin >> 2, c4 = lin & 3;
            int kk = k0 + (c4 << 2);
            float4 v = *(const float4*)(g_h1 + (size_t)(rowTile + r) * C1 + kk);
            float4 a = *(const float4*)(g_a1 + kk);
            float4 c = *(const float4*)(g_c1 + kk);
            v.x = fmaxf(fmaf(v.x, a.x, c.x), 0.f);
            v.y = fmaxf(fmaf(v.y, a.y, c.y), 0.f);
            v.z = fmaxf(fmaf(v.z, a.z, c.z), 0.f);
            v.w = fmaxf(fmaf(v.w, a.w, c.w), 0.f);
            As[(c4 << 2) + 0][r] = v.x; As[(c4 << 2) + 1][r] = v.y;
            As[(c4 << 2) + 2][r] = v.z; As[(c4 << 2) + 3][r] = v.w;
        }
#pragma unroll
        for (int l = 0; l < 2; l++) {
            int lin = tid + (l << 8);
            int o = lin >> 2, c4 = lin & 3;
            float4 v = *(const float4*)(w2 + (size_t)o * C1 + k0 + (c4 << 2));
            Bs[(c4 << 2) + 0][o] = v.x; Bs[(c4 << 2) + 1][o] = v.y;
            Bs[(c4 << 2) + 2][o] = v.z; Bs[(c4 << 2) + 3][o] = v.w;
        }
        __syncthreads();
#pragma unroll
        for (int k = 0; k < 16; k++) {
            float af[8], bf[8];
            *(float4*)(af)     = *(const float4*)&As[k][tr << 2];
            *(float4*)(af + 4) = *(const float4*)&As[k][64 + (tr << 2)];
            *(float4*)(bf)     = *(const float4*)&Bs[k][tc << 2];
            *(float4*)(bf + 4) = *(const float4*)&Bs[k][64 + (tc << 2)];
#pragma unroll
            for (int i = 0; i < 8; i++)
#pragma unroll
                for (int j = 0; j < 8; j++)
                    acc[i][j] = fmaf(af[i], bf[j], acc[i][j]);
        }
        __syncthreads();
    }
    float bv[8];
#pragma unroll
    for (int j = 0; j < 8; j++) {
        int cl = (j < 4) ? (tc * 4 + j) : (64 + tc * 4 + j - 4);
        bv[j] = bias[cl];
    }
    float csum[8] = {}, csq[8] = {};
#pragma unroll
    for (int i = 0; i < 8; i++) {
        int rl = (i < 4) ? (tr * 4 + i) : (64 + tr * 4 + i - 4);
        int mg = rowTile + rl;
        float o[8];
#pragma unroll
        for (int j = 0; j < 8; j++) {
            float v = acc[i][j] + bv[j];
            o[j] = v;
            csum[j] += v;
            csq[j] = fmaf(v, v, csq[j]);
        }
        float* dst = g_h2 + (size_t)mg * C2;
        *(float4*)(dst + tc * 4)      = make_float4(o[0], o[1], o[2], o[3]);
        *(float4*)(dst + 64 + tc * 4) = make_float4(o[4], o[5], o[6], o[7]);
    }
    __syncthreads();
#pragma unroll
    for (int j = 0; j < 8; j++) {
        int cl = (j < 4) ? (tc * 4 + j) : (64 + tc * 4 + j - 4);
        As[tr][cl] = csum[j];
        Bs[tr][cl] = csq[j];
    }
    __syncthreads();
    if (tid < 128) {
        float s = 0.f, q = 0.f;
#pragma unroll
        for (int t = 0; t < 16; t++) { s += As[t][tid]; q += Bs[t][tid]; }
        atomicAdd(&g_bn2s[tid], s);
        atomicAdd(&g_bn2q[tid], q);
    }
}

// ---------------- avg/max pool over N of relu(bn2(h2)) ----------------
__global__ __launch_bounds__(1024) void pool_kernel() {
    int b = blockIdx.x;
    int c = threadIdx.x & 127;
    int seg = threadIdx.x >> 7;                       // 0..7
    int n0 = blockIdx.y * 1024;
    float a = g_a2[c], cc = g_c2[c];
    float sum = 0.f, mx = 0.f;
    const float* base = g_h2 + ((size_t)b * NN + n0) * C2;
    for (int r = seg; r < 1024; r += 8) {
        float v = fmaxf(fmaf(base[(size_t)r * C2 + c], a, cc), 0.f);
        sum += v;
        mx = fmaxf(mx, v);
    }
    __shared__ float ss[8][128];
    __shared__ float sm[8][128];
    ss[seg][c] = sum;
    sm[seg][c] = mx;
    __syncthreads();
    if (seg == 0) {
#pragma unroll
        for (int t = 1; t < 8; t++) { sum += ss[t][c]; mx = fmaxf(mx, sm[t][c]); }
        atomicAdd(&g_poolsum[b * C2 + c], sum);
        atomicMax(&g_poolmax[b * C2 + c], __float_as_int(mx));
    }
}

// ---------------- SE attention MLP + sigmoid ----------------
__global__ __launch_bounds__(1024) void se_kernel(
    const float* __restrict__ fa1, const float* __restrict__ fa2) {
    __shared__ float ha[8][16], hm[8][16];
    int t = threadIdx.x;
    if (t < 128) {
        int b = t >> 4, j = t & 15;
        const float invN = 1.0f / (float)NN;
        float sa = 0.f, smx = 0.f;
        for (int c = 0; c < C2; c++) {
            float f = fa1[j * C2 + c];
            sa  = fmaf(g_poolsum[b * C2 + c] * invN, f, sa);
            smx = fmaf(__int_as_float(g_poolmax[b * C2 + c]), f, smx);
        }
        ha[b][j] = fmaxf(sa, 0.f);
        hm[b][j] = fmaxf(smx, 0.f);
    }
    __syncthreads();
    int b = t >> 7, c = t & 127;
    float s = 0.f;
#pragma unroll
    for (int j = 0; j < 16; j++)
        s = fmaf(ha[b][j] + hm[b][j], fa2[c * 16 + j], s);
    g_scale[b * C2 + c] = 1.f / (1.f + expf(-s));
}

// ---------------- final: out = relu(bn2(h2)) * scale ----------------
__global__ __launch_bounds__(256) void final_kernel(float* __restrict__ out) {
    int i = blockIdx.x * blockDim.x + threadIdx.x;    // float4 index
    size_t e = (size_t)i << 2;
    int c = (int)(e & 127);
    int b = (int)(e >> 21);                            // / (NN*C2)
    float4 h = *(const float4*)(g_h2 + e);
    float4 a = *(const float4*)(g_a2 + c);
    float4 cc = *(const float4*)(g_c2 + c);
    float4 s = *(const float4*)(g_scale + b * C2 + c);
    float4 r;
    r.x = fmaxf(fmaf(h.x, a.x, cc.x), 0.f) * s.x;
    r.y = fmaxf(fmaf(h.y, a.y, cc.y), 0.f) * s.y;
    r.z = fmaxf(fmaf(h.z, a.z, cc.z), 0.f) * s.z;
    r.w = fmaxf(fmaf(h.w, a.w, cc.w), 0.f) * s.w;
    *(float4*)(out + e) = r;
}

// ---------------- launch ----------------
extern "C" void kernel_launch(void* const* d_in, const int* in_sizes, int n_in,
                              void* d_out, int out_size) {
    const float* xyz1    = (const float*)d_in[0];
    const float* xyz2    = (const float*)d_in[1];
    const float* points1 = (const float*)d_in[2];
    const float* points2 = (const float*)d_in[3];
    const float* w1      = (const float*)d_in[4];
    const float* b1      = (const float*)d_in[5];
    const float* g1      = (const float*)d_in[6];
    const float* be1     = (const float*)d_in[7];
    const float* w2      = (const float*)d_in[8];
    const float* b2      = (const float*)d_in[9];
    const float* g2      = (const float*)d_in[10];
    const float* be2     = (const float*)d_in[11];
    const float* fa1     = (const float*)d_in[12];
    const float* fa2     = (const float*)d_in[13];
    float* out = (float*)d_out;

    init_kernel<<<1, 1024>>>();
    nn3_kernel<<<dim3(NN / 256, BB), 256>>>(xyz1, xyz2);
    p2w_kernel<<<dim3(M2 / 128, C1 / 128), 256>>>(points2, w1);
    gemm1_kernel<<<dim3(MM / 128, C1 / 128), 256>>>(points1, w1, b1);
    bnparam_kernel<<<1, 256>>>(g1, be1, 0);
    gemm2_kernel<<<dim3(MM / 128, 1), 256>>>(w2, b2);
    bnparam_kernel<<<1, 256>>>(g2, be2, 1);
    pool_kernel<<<dim3(BB, 16), 1024>>>();
    se_kernel<<<1, 1024>>>(fa1, fa2);
    final_kernel<<<(MM * C2 / 4) / 256, 256>>>(out);
}

// round 3
// speedup vs baseline: 1.0247x; 1.0247x over previous
#include <cuda_runtime.h>

#define BN_EPS   1e-5f
#define DIST_EPS 1e-8f

#define BB 8
#define NN 16384
#define SS 2048
#define D1C 128
#define D2C 256
#define MM (BB*NN)      /* 131072 */
#define M2 (BB*SS)      /* 16384 */
#define C1 256
#define C2 128
#define W1STRIDE 384

typedef unsigned long long ull;

// ---------------- packed f32x2 helpers ----------------
__device__ __forceinline__ ull fma2(ull a, ull b, ull c) {
    ull d;
    asm("fma.rn.f32x2 %0, %1, %2, %3;" : "=l"(d) : "l"(a), "l"(b), "l"(c));
    return d;
}
__device__ __forceinline__ ull dup2(float x) {
    ull d;
    asm("mov.b64 %0, {%1, %1};" : "=l"(d) : "f"(x));
    return d;
}
union F4U { float4 f; ull u[2]; };

// ---------------- scratch (device globals; no allocations) ----------------
__device__ __align__(16) float g_p2w[(size_t)M2 * C1];       // 16 MB (L2-resident)
__device__ __align__(16) float g_h1[(size_t)MM * C1];        // 134 MB
__device__ __align__(16) float g_h2[(size_t)MM * C2];        // 67 MB
__device__ int   g_idx3[MM * 3];
__device__ float g_w3[MM * 3];
__device__ float g_bn1s[C1], g_bn1q[C1];
__device__ float g_bn2s[C2], g_bn2q[C2];
__device__ __align__(16) float g_a1[C1], g_c1[C1];
__device__ __align__(16) float g_a2[C2], g_c2[C2];
__device__ float g_poolsum[BB * C2];
__device__ int   g_poolmax[BB * C2];          // float-as-int, all values >= 0
__device__ __align__(16) float g_scale[BB * C2];

// ---------------- init: zero per-replay accumulators ----------------
__global__ void init_kernel() {
    int t = threadIdx.x;
    if (t < C1) { g_bn1s[t] = 0.f; g_bn1q[t] = 0.f; }
    if (t < C2) { g_bn2s[t] = 0.f; g_bn2q[t] = 0.f; }
    for (int i = t; i < BB * C2; i += blockDim.x) {
        g_poolsum[i] = 0.f;
        g_poolmax[i] = 0;
    }
}

// ---------------- 3-NN search ----------------
__global__ __launch_bounds__(256) void nn3_kernel(
    const float* __restrict__ xyz1, const float* __restrict__ xyz2) {
    __shared__ float sx[SS], sy[SS], sz[SS];
    int b = blockIdx.y;
    const float* x2 = xyz2 + (size_t)b * SS * 3;
    for (int j = threadIdx.x; j < SS; j += blockDim.x) {
        sx[j] = x2[j * 3 + 0];
        sy[j] = x2[j * 3 + 1];
        sz[j] = x2[j * 3 + 2];
    }
    __syncthreads();
    int n = blockIdx.x * blockDim.x + threadIdx.x;
    int m = b * NN + n;
    float px = xyz1[(size_t)m * 3 + 0];
    float py = xyz1[(size_t)m * 3 + 1];
    float pz = xyz1[(size_t)m * 3 + 2];
    float d0 = 1e30f, d1 = 1e30f, d2 = 1e30f;
    int i0 = 0, i1 = 0, i2 = 0;
#pragma unroll 4
    for (int j = 0; j < SS; j++) {
        float dx = px - sx[j], dy = py - sy[j], dz = pz - sz[j];
        float d = fmaf(dx, dx, fmaf(dy, dy, dz * dz));
        if (d < d2) {
            if (d < d1) {
                d2 = d1; i2 = i1;
                if (d < d0) { d1 = d0; i1 = i0; d0 = d; i0 = j; }
                else        { d1 = d;  i1 = j; }
            } else { d2 = d; i2 = j; }
        }
    }
    float r0 = 1.f / (d0 + DIST_EPS);
    float r1 = 1.f / (d1 + DIST_EPS);
    float r2 = 1.f / (d2 + DIST_EPS);
    float rs = 1.f / (r0 + r1 + r2);
    g_idx3[m * 3 + 0] = i0; g_idx3[m * 3 + 1] = i1; g_idx3[m * 3 + 2] = i2;
    g_w3[m * 3 + 0] = r0 * rs; g_w3[m * 3 + 1] = r1 * rs; g_w3[m * 3 + 2] = r2 * rs;
}

// ======== shared inner-product step (f32x2), used by all GEMMs ========
__device__ __forceinline__ void mma_step(const float (*As)[128], const float (*Bs)[128],
                                         int tr, int tc, ull acc2[8][4]) {
#pragma unroll
    for (int k = 0; k < 16; k++) {
        float af[8];
        *(float4*)(af)     = *(const float4*)&As[k][tr << 2];
        *(float4*)(af + 4) = *(const float4*)&As[k][64 + (tr << 2)];
        F4U b0, b1;
        b0.f = *(const float4*)&Bs[k][tc << 2];
        b1.f = *(const float4*)&Bs[k][64 + (tc << 2)];
        ull bv[4] = { b0.u[0], b0.u[1], b1.u[0], b1.u[1] };
#pragma unroll
        for (int i = 0; i < 8; i++) {
            ull a2 = dup2(af[i]);
#pragma unroll
            for (int j = 0; j < 4; j++)
                acc2[i][j] = fma2(a2, bv[j], acc2[i][j]);
        }
    }
}

// ---------------- P2W: [16384,256] x W1b[256->256]  (w1 cols 128..383) ----------------
__global__ __launch_bounds__(256, 2) void p2w_kernel(
    const float* __restrict__ points2, const float* __restrict__ w1) {
    __shared__ float As[2][16][128];
    __shared__ float Bs[2][16][128];
    int tid = threadIdx.x;
    int tr = tid >> 4, tc = tid & 15;
    int rowTile = blockIdx.x << 7;
    int colTile = blockIdx.y << 7;
    int lr0 = tid >> 2,         lc0 = (tid & 3) << 2;
    int lr1 = (tid + 256) >> 2, lc1 = lc0;
    const float* aP0 = points2 + (size_t)(rowTile + lr0) * D2C + lc0;
    const float* aP1 = points2 + (size_t)(rowTile + lr1) * D2C + lc1;
    const float* bP0 = w1 + (size_t)(colTile + lr0) * W1STRIDE + D1C + lc0;
    const float* bP1 = w1 + (size_t)(colTile + lr1) * W1STRIDE + D1C + lc1;
    float4 pa0 = *(const float4*)aP0, pa1 = *(const float4*)aP1;
    float4 pb0 = *(const float4*)bP0, pb1 = *(const float4*)bP1;
    ull acc2[8][4] = {};
    int cur = 0;
#pragma unroll 1
    for (int t = 0; t < 16; t++) {
        As[cur][lc0 + 0][lr0] = pa0.x; As[cur][lc0 + 1][lr0] = pa0.y;
        As[cur][lc0 + 2][lr0] = pa0.z; As[cur][lc0 + 3][lr0] = pa0.w;
        As[cur][lc1 + 0][lr1] = pa1.x; As[cur][lc1 + 1][lr1] = pa1.y;
        As[cur][lc1 + 2][lr1] = pa1.z; As[cur][lc1 + 3][lr1] = pa1.w;
        Bs[cur][lc0 + 0][lr0] = pb0.x; Bs[cur][lc0 + 1][lr0] = pb0.y;
        Bs[cur][lc0 + 2][lr0] = pb0.z; Bs[cur][lc0 + 3][lr0] = pb0.w;
        Bs[cur][lc1 + 0][lr1] = pb1.x; Bs[cur][lc1 + 1][lr1] = pb1.y;
        Bs[cur][lc1 + 2][lr1] = pb1.z; Bs[cur][lc1 + 3][lr1] = pb1.w;
        __syncthreads();
        if (t < 15) {
            int k0 = (t + 1) << 4;
            pa0 = *(const float4*)(aP0 + k0); pa1 = *(const float4*)(aP1 + k0);
            pb0 = *(const float4*)(bP0 + k0); pb1 = *(const float4*)(bP1 + k0);
        }
        mma_step(As[cur], Bs[cur], tr, tc, acc2);
        cur ^= 1;
        if (t < 15) __syncthreads();
    }
#pragma unroll
    for (int i = 0; i < 8; i++) {
        int rl = (i < 4) ? (tr * 4 + i) : (64 + tr * 4 + i - 4);
        F4U o0, o1;
        o0.u[0] = acc2[i][0]; o0.u[1] = acc2[i][1];
        o1.u[0] = acc2[i][2]; o1.u[1] = acc2[i][3];
        float* dst = g_p2w + (size_t)(rowTile + rl) * C1 + colTile;
        *(float4*)(dst + tc * 4)      = o0.f;
        *(float4*)(dst + 64 + tc * 4) = o1.f;
    }
}

// ---- GEMM1: points1[M,128] x W1a[128->256] + gathered P2W + bias; bn-stats epilogue ----
__global__ __launch_bounds__(256, 2) void gemm1_kernel(
    const float* __restrict__ points1, const float* __restrict__ w1,
    const float* __restrict__ bias) {
    __shared__ float As[2][16][128];
    __shared__ float Bs[2][16][128];
    __shared__ int   sIdx[128][3];
    __shared__ float sW[128][3];
    int tid = threadIdx.x;
    int tr = tid >> 4, tc = tid & 15;
    int rowTile = blockIdx.x << 7;
    int colTile = blockIdx.y << 7;
    int bBlk = rowTile >> 14;
    if (tid < 128) {
        int m = rowTile + tid;
        sIdx[tid][0] = g_idx3[m * 3 + 0];
        sIdx[tid][1] = g_idx3[m * 3 + 1];
        sIdx[tid][2] = g_idx3[m * 3 + 2];
        sW[tid][0] = g_w3[m * 3 + 0];
        sW[tid][1] = g_w3[m * 3 + 1];
        sW[tid][2] = g_w3[m * 3 + 2];
    }
    int lr0 = tid >> 2,         lc0 = (tid & 3) << 2;
    int lr1 = (tid + 256) >> 2, lc1 = lc0;
    const float* aP0 = points1 + (size_t)(rowTile + lr0) * D1C + lc0;
    const float* aP1 = points1 + (size_t)(rowTile + lr1) * D1C + lc1;
    const float* bP0 = w1 + (size_t)(colTile + lr0) * W1STRIDE + lc0;
    const float* bP1 = w1 + (size_t)(colTile + lr1) * W1STRIDE + lc1;
    float4 pa0 = *(const float4*)aP0, pa1 = *(const float4*)aP1;
    float4 pb0 = *(const float4*)bP0, pb1 = *(const float4*)bP1;
    ull acc2[8][4] = {};
    int cur = 0;
#pragma unroll 1
    for (int t = 0; t < 8; t++) {
        As[cur][lc0 + 0][lr0] = pa0.x; As[cur][lc0 + 1][lr0] = pa0.y;
        As[cur][lc0 + 2][lr0] = pa0.z; As[cur][lc0 + 3][lr0] = pa0.w;
        As[cur][lc1 + 0][lr1] = pa1.x; As[cur][lc1 + 1][lr1] = pa1.y;
        As[cur][lc1 + 2][lr1] = pa1.z; As[cur][lc1 + 3][lr1] = pa1.w;
        Bs[cur][lc0 + 0][lr0] = pb0.x; Bs[cur][lc0 + 1][lr0] = pb0.y;
        Bs[cur][lc0 + 2][lr0] = pb0.z; Bs[cur][lc0 + 3][lr0] = pb0.w;
        Bs[cur][lc1 + 0][lr1] = pb1.x; Bs[cur][lc1 + 1][lr1] = pb1.y;
        Bs[cur][lc1 + 2][lr1] = pb1.z; Bs[cur][lc1 + 3][lr1] = pb1.w;
        __syncthreads();
        if (t < 7) {
            int k0 = (t + 1) << 4;
            pa0 = *(const float4*)(aP0 + k0); pa1 = *(const float4*)(aP1 + k0);
            pb0 = *(const float4*)(bP0 + k0); pb1 = *(const float4*)(bP1 + k0);
        }
        mma_step(As[cur], Bs[cur], tr, tc, acc2);
        cur ^= 1;
        if (t < 7) __syncthreads();
    }
    float bv[8];
#pragma unroll
    for (int j = 0; j < 8; j++) {
        int cl = (j < 4) ? (tc * 4 + j) : (64 + tc * 4 + j - 4);
        bv[j] = bias[colTile + cl];
    }
    const float* Pbase = g_p2w + (size_t)bBlk * SS * C1 + colTile;
    float csum[8] = {}, csq[8] = {};
#pragma unroll
    for (int i = 0; i < 8; i++) {
        int rl = (i < 4) ? (tr * 4 + i) : (64 + tr * 4 + i - 4);
        int mg = rowTile + rl;
        float w0 = sW[rl][0], w1v = sW[rl][1], w2v = sW[rl][2];
        const float* P0 = Pbase + (size_t)sIdx[rl][0] * C1;
        const float* P1 = Pbase + (size_t)sIdx[rl][1] * C1;
        const float* P2 = Pbase + (size_t)sIdx[rl][2] * C1;
        float4 a0 = *(const float4*)(P0 + tc * 4);
        float4 a1 = *(const float4*)(P1 + tc * 4);
        float4 a2 = *(const float4*)(P2 + tc * 4);
        float4 e0 = *(const float4*)(P0 + 64 + tc * 4);
        float4 e1 = *(const float4*)(P1 + 64 + tc * 4);
        float4 e2 = *(const float4*)(P2 + 64 + tc * 4);
        F4U o0, o1;
        o0.u[0] = acc2[i][0]; o0.u[1] = acc2[i][1];
        o1.u[0] = acc2[i][2]; o1.u[1] = acc2[i][3];
        float acc8[8] = { o0.f.x, o0.f.y, o0.f.z, o0.f.w,
                          o1.f.x, o1.f.y, o1.f.z, o1.f.w };
        float gth[8];
        gth[0] = w0 * a0.x + w1v * a1.x + w2v * a2.x;
        gth[1] = w0 * a0.y + w1v * a1.y + w2v * a2.y;
        gth[2] = w0 * a0.z + w1v * a1.z + w2v * a2.z;
        gth[3] = w0 * a0.w + w1v * a1.w + w2v * a2.w;
        gth[4] = w0 * e0.x + w1v * e1.x + w2v * e2.x;
        gth[5] = w0 * e0.y + w1v * e1.y + w2v * e2.y;
        gth[6] = w0 * e0.z + w1v * e1.z + w2v * e2.z;
        gth[7] = w0 * e0.w + w1v * e1.w + w2v * e2.w;
        float o[8];
#pragma unroll
        for (int j = 0; j < 8; j++) {
            float v = acc8[j] + bv[j] + gth[j];
            o[j] = v;
            csum[j] += v;
            csq[j] = fmaf(v, v, csq[j]);
        }
        float* dst = g_h1 + (size_t)mg * C1 + colTile;
        *(float4*)(dst + tc * 4)      = make_float4(o[0], o[1], o[2], o[3]);
        *(float4*)(dst + 64 + tc * 4) = make_float4(o[4], o[5], o[6], o[7]);
    }
    __syncthreads();
#pragma unroll
    for (int j = 0; j < 8; j++) {
        int cl = (j < 4) ? (tc * 4 + j) : (64 + tc * 4 + j - 4);
        As[0][tr][cl] = csum[j];
        Bs[0][tr][cl] = csq[j];
    }
    __syncthreads();
    if (tid < 128) {
        float s = 0.f, q = 0.f;
#pragma unroll
        for (int t = 0; t < 16; t++) { s += As[0][t][tid]; q += Bs[0][t][tid]; }
        atomicAdd(&g_bn1s[colTile + tid], s);
        atomicAdd(&g_bn1q[colTile + tid], q);
    }
}

// ---------------- bn param: sums -> (a, c) affine ----------------
__global__ void bnparam_kernel(const float* __restrict__ g,
                               const float* __restrict__ be, int which) {
    int i = threadIdx.x;
    const float invM = 1.0f / (float)MM;
    if (which == 0) {
        if (i < C1) {
            float mu = g_bn1s[i] * invM;
            float var = g_bn1q[i] * invM - mu * mu;
            float a = g[i] * rsqrtf(var + BN_EPS);
            g_a1[i] = a;
            g_c1[i] = fmaf(-mu, a, be[i]);
        }
    } else {
        if (i < C2) {
            float mu = g_bn2s[i] * invM;
            float var = g_bn2q[i] * invM - mu * mu;
            float a = g[i] * rsqrtf(var + BN_EPS);
            g_a2[i] = a;
            g_c2[i] = fmaf(-mu, a, be[i]);
        }
    }
}

// ---------------- GEMM2: relu(bn1(h1)) x [256->128] + bias, bn-stats epilogue ----------------
__global__ __launch_bounds__(256, 2) void gemm2_kernel(
    const float* __restrict__ w2, const float* __restrict__ bias) {
    __shared__ float As[2][16][128];
    __shared__ float Bs[2][16][128];
    int tid = threadIdx.x;
    int tr = tid >> 4, tc = tid & 15;
    int rowTile = blockIdx.x << 7;
    int lr0 = tid >> 2,         lc0 = (tid & 3) << 2;
    int lr1 = (tid + 256) >> 2, lc1 = lc0;
    const float* aP0 = g_h1 + (size_t)(rowTile + lr0) * C1 + lc0;
    const float* aP1 = g_h1 + (size_t)(rowTile + lr1) * C1 + lc1;
    const float* bP0 = w2 + (size_t)lr0 * C1 + lc0;
    const float* bP1 = w2 + (size_t)lr1 * C1 + lc1;
    float4 pa0 = *(const float4*)aP0, pa1 = *(const float4*)aP1;
    float4 pb0 = *(const float4*)bP0, pb1 = *(const float4*)bP1;
    ull acc2[8][4] = {};
    int cur = 0;
#pragma unroll 1
    for (int t = 0; t < 16; t++) {
        int kk = t << 4;
        {
            float4 a0 = *(const float4*)(g_a1 + kk + lc0);
            float4 c0 = *(const float4*)(g_c1 + kk + lc0);
            float4 v = pa0;
            v.x = fmaxf(fmaf(v.x, a0.x, c0.x), 0.f);
            v.y = fmaxf(fmaf(v.y, a0.y, c0.y), 0.f);
            v.z = fmaxf(fmaf(v.z, a0.z, c0.z), 0.f);
            v.w = fmaxf(fmaf(v.w, a0.w, c0.w), 0.f);
            As[cur][lc0 + 0][lr0] = v.x; As[cur][lc0 + 1][lr0] = v.y;
            As[cur][lc0 + 2][lr0] = v.z; As[cur][lc0 + 3][lr0] = v.w;
            float4 v1 = pa1;
            v1.x = fmaxf(fmaf(v1.x, a0.x, c0.x), 0.f);
            v1.y = fmaxf(fmaf(v1.y, a0.y, c0.y), 0.f);
            v1.z = fmaxf(fmaf(v1.z, a0.z, c0.z), 0.f);
            v1.w = fmaxf(fmaf(v1.w, a0.w, c0.w), 0.f);
            As[cur][lc1 + 0][lr1] = v1.x; As[cur][lc1 + 1][lr1] = v1.y;
            As[cur][lc1 + 2][lr1] = v1.z; As[cur][lc1 + 3][lr1] = v1.w;
        }
        Bs[cur][lc0 + 0][lr0] = pb0.x; Bs[cur][lc0 + 1][lr0] = pb0.y;
        Bs[cur][lc0 + 2][lr0] = pb0.z; Bs[cur][lc0 + 3][lr0] = pb0.w;
        Bs[cur][lc1 + 0][lr1] = pb1.x; Bs[cur][lc1 + 1][lr1] = pb1.y;
        Bs[cur][lc1 + 2][lr1] = pb1.z; Bs[cur][lc1 + 3][lr1] = pb1.w;
        __syncthreads();
        if (t < 15) {
            int k0 = (t + 1) << 4;
            pa0 = *(const float4*)(aP0 + k0); pa1 = *(const float4*)(aP1 + k0);
            pb0 = *(const float4*)(bP0 + k0); pb1 = *(const float4*)(bP1 + k0);
        }
        mma_step(As[cur], Bs[cur], tr, tc, acc2);
        cur ^= 1;
        if (t < 15) __syncthreads();
    }
    float bv[8];
#pragma unroll
    for (int j = 0; j < 8; j++) {
        int cl = (j < 4) ? (tc * 4 + j) : (64 + tc * 4 + j - 4);
        bv[j] = bias[cl];
    }
    float csum[8] = {}, csq[8] = {};
#pragma unroll
    for (int i = 0; i < 8; i++) {
        int rl = (i < 4) ? (tr * 4 + i) : (64 + tr * 4 + i - 4);
        int mg = rowTile + rl;
        F4U o0, o1;
        o0.u[0] = acc2[i][0]; o0.u[1] = acc2[i][1];
        o1.u[0] = acc2[i][2]; o1.u[1] = acc2[i][3];
        float acc8[8] = { o0.f.x, o0.f.y, o0.f.z, o0.f.w,
                          o1.f.x, o1.f.y, o1.f.z, o1.f.w };
        float o[8];
#pragma unroll
        for (int j = 0; j < 8; j++) {
            float v = acc8[j] + bv[j];
            o[j] = v;
            csum[j] += v;
            csq[j] = fmaf(v, v, csq[j]);
        }
        float* dst = g_h2 + (size_t)mg * C2;
        *(float4*)(dst + tc * 4)      = make_float4(o[0], o[1], o[2], o[3]);
        *(float4*)(dst + 64 + tc * 4) = make_float4(o[4], o[5], o[6], o[7]);
    }
    __syncthreads();
#pragma unroll
    for (int j = 0; j < 8; j++) {
        int cl = (j < 4) ? (tc * 4 + j) : (64 + tc * 4 + j - 4);
        As[0][tr][cl] = csum[j];
        Bs[0][tr][cl] = csq[j];
    }
    __syncthreads();
    if (tid < 128) {
        float s = 0.f, q = 0.f;
#pragma unroll
        for (int t = 0; t < 16; t++) { s += As[0][t][tid]; q += Bs[0][t][tid]; }
        atomicAdd(&g_bn2s[tid], s);
        atomicAdd(&g_bn2q[tid], q);
    }
}

// ---------------- avg/max pool over N of relu(bn2(h2)) ----------------
__global__ __launch_bounds__(1024) void pool_kernel() {
    int b = blockIdx.x;
    int c = threadIdx.x & 127;
    int seg = threadIdx.x >> 7;                       // 0..7
    int n0 = blockIdx.y * 1024;
    float a = g_a2[c], cc = g_c2[c];
    float sum = 0.f, mx = 0.f;
    const float* base = g_h2 + ((size_t)b * NN + n0) * C2;
    for (int r = seg; r < 1024; r += 8) {
        float v = fmaxf(fmaf(base[(size_t)r * C2 + c], a, cc), 0.f);
        sum += v;
        mx = fmaxf(mx, v);
    }
    __shared__ float ss[8][128];
    __shared__ float sm[8][128];
    ss[seg][c] = sum;
    sm[seg][c] = mx;
    __syncthreads();
    if (seg == 0) {
#pragma unroll
        for (int t = 1; t < 8; t++) { sum += ss[t][c]; mx = fmaxf(mx, sm[t][c]); }
        atomicAdd(&g_poolsum[b * C2 + c], sum);
        atomicMax(&g_poolmax[b * C2 + c], __float_as_int(mx));
    }
}

// ---------------- SE attention MLP + sigmoid ----------------
__global__ __launch_bounds__(1024) void se_kernel(
    const float* __restrict__ fa1, const float* __restrict__ fa2) {
    __shared__ float ha[8][16], hm[8][16];
    int t = threadIdx.x;
    if (t < 128) {
        int b = t >> 4, j = t & 15;
        const float invN = 1.0f / (float)NN;
        float sa = 0.f, smx = 0.f;
        for (int c = 0; c < C2; c++) {
            float f = fa1[j * C2 + c];
            sa  = fmaf(g_poolsum[b * C2 + c] * invN, f, sa);
            smx = fmaf(__int_as_float(g_poolmax[b * C2 + c]), f, smx);
        }
        ha[b][j] = fmaxf(sa, 0.f);
        hm[b][j] = fmaxf(smx, 0.f);
    }
    __syncthreads();
    int b = t >> 7, c = t & 127;
    float s = 0.f;
#pragma unroll
    for (int j = 0; j < 16; j++)
        s = fmaf(ha[b][j] + hm[b][j], fa2[c * 16 + j], s);
    g_scale[b * C2 + c] = 1.f / (1.f + expf(-s));
}

// ---------------- final: out = relu(bn2(h2)) * scale ----------------
__global__ __launch_bounds__(256) void final_kernel(float* __restrict__ out) {
    int i = blockIdx.x * blockDim.x + threadIdx.x;    // float4 index
    size_t e = (size_t)i << 2;
    int c = (int)(e & 127);
    int b = (int)(e >> 21);                            // / (NN*C2)
    float4 h = *(const float4*)(g_h2 + e);
    float4 a = *(const float4*)(g_a2 + c);
    float4 cc = *(const float4*)(g_c2 + c);
    float4 s = *(const float4*)(g_scale + b * C2 + c);
    float4 r;
    r.x = fmaxf(fmaf(h.x, a.x, cc.x), 0.f) * s.x;
    r.y = fmaxf(fmaf(h.y, a.y, cc.y), 0.f) * s.y;
    r.z = fmaxf(fmaf(h.z, a.z, cc.z), 0.f) * s.z;
    r.w = fmaxf(fmaf(h.w, a.w, cc.w), 0.f) * s.w;
    *(float4*)(out + e) = r;
}

// ---------------- launch ----------------
extern "C" void kernel_launch(void* const* d_in, const int* in_sizes, int n_in,
                              void* d_out, int out_size) {
    const float* xyz1    = (const float*)d_in[0];
    const float* xyz2    = (const float*)d_in[1];
    const float* points1 = (const float*)d_in[2];
    const float* points2 = (const float*)d_in[3];
    const float* w1      = (const float*)d_in[4];
    const float* b1      = (const float*)d_in[5];
    const float* g1      = (const float*)d_in[6];
    const float* be1     = (const float*)d_in[7];
    const float* w2      = (const float*)d_in[8];
    const float* b2      = (const float*)d_in[9];
    const float* g2      = (const float*)d_in[10];
    const float* be2     = (const float*)d_in[11];
    const float* fa1     = (const float*)d_in[12];
    const float* fa2     = (const float*)d_in[13];
    float* out = (float*)d_out;

    init_kernel<<<1, 1024>>>();
    nn3_kernel<<<dim3(NN / 256, BB), 256>>>(xyz1, xyz2);
    p2w_kernel<<<dim3(M2 / 128, C1 / 128), 256>>>(points2, w1);
    gemm1_kernel<<<dim3(MM / 128, C1 / 128), 256>>>(points1, w1, b1);
    bnparam_kernel<<<1, 256>>>(g1, be1, 0);
    gemm2_kernel<<<dim3(MM / 128, 1), 256>>>(w2, b2);
    bnparam_kernel<<<1, 256>>>(g2, be2, 1);
    pool_kernel<<<dim3(BB, 16), 1024>>>();
    se_kernel<<<1, 1024>>>(fa1, fa2);
    final_kernel<<<(MM * C2 / 4) / 256, 256>>>(out);
}